// round 2
// baseline (speedup 1.0000x reference)
#include <cuda_runtime.h>
#include <math.h>

#define SQ   256   // sequence length
#define BBV  64    // batch
#define DIN  300   // embed dim
#define HHV  256   // lstm hidden
#define G4   1024  // 4*H
#define TT   34    // tags

// ---------------- scratch (static __device__ globals; no allocations) ------
__device__ float g_xg_f[SQ * BBV * G4];     // 64 MB  input-proj gates, fwd
__device__ float g_xg_b[SQ * BBV * G4];     // 64 MB  input-proj gates, bwd
__device__ float g_h_f [SQ * BBV * HHV];    // 16 MB  h history, fwd
__device__ float g_h_b [SQ * BBV * HHV];    // 16 MB  h history, bwd
__device__ float g_emit[BBV * SQ * TT];     // 2.2 MB emissions [b][s][t]
__device__ float g_llh [BBV];
__device__ unsigned long long g_bar[2];     // monotonic barrier counters

// ============================================================================
// Kernel 1: fused embedding-gather + input projection SGEMM.
//   xg[s][b][j] = sum_k emb[batch[b][s]][k] * w_ih[j][k] + bias[j]
// C is [M=16384 (m = s*64+b)] x [N=2048 (fwd 0..1023, bwd 1024..2047)], K=300.
// 128x128 block tile, 8x8 per thread, k-step 8.
// ============================================================================
__global__ void __launch_bounds__(256) input_gemm(
    const float* __restrict__ emb, const int* __restrict__ batch,
    const float* __restrict__ wf, const float* __restrict__ bf,
    const float* __restrict__ wb, const float* __restrict__ bb)
{
    __shared__ float As[8][128];
    __shared__ float Bs[8][128];

    int tid = threadIdx.x;
    int bm  = blockIdx.y * 128;
    int bnG = blockIdx.x * 128;
    int dir = (bnG >= G4) ? 1 : 0;
    int j0  = bnG - dir * G4;
    const float* W    = dir ? wb : wf;
    const float* bias = dir ? bb : bf;
    float*       outp = dir ? g_xg_b : g_xg_f;

    int am = tid & 127;           // row within tile (A: m, B: j)
    int ak = (tid >> 7) << 2;     // k base (0 or 4)
    int mg = bm + am;
    int token = batch[(mg & 63) * SQ + (mg >> 6)];   // batch[b][s], m = s*64+b
    const float* arow = emb + token * DIN;
    const float* wrow = W + (j0 + am) * DIN;

    int tx = tid & 15, ty = tid >> 4;
    float acc[8][8];
#pragma unroll
    for (int i = 0; i < 8; ++i)
#pragma unroll
        for (int j = 0; j < 8; ++j) acc[i][j] = 0.f;

    for (int kk = 0; kk < DIN; kk += 8) {
#pragma unroll
        for (int q = 0; q < 4; ++q) {
            int k = kk + ak + q;
            float av = (k < DIN) ? arow[k] : 0.f;
            float bv = (k < DIN) ? wrow[k] : 0.f;
            As[ak + q][am] = av;
            Bs[ak + q][am] = bv;
        }
        __syncthreads();
#pragma unroll
        for (int k = 0; k < 8; ++k) {
            float4 a0 = *(const float4*)&As[k][ty * 8];
            float4 a1 = *(const float4*)&As[k][ty * 8 + 4];
            float4 b0 = *(const float4*)&Bs[k][tx * 8];
            float4 b1 = *(const float4*)&Bs[k][tx * 8 + 4];
            float av[8] = {a0.x, a0.y, a0.z, a0.w, a1.x, a1.y, a1.z, a1.w};
            float bv[8] = {b0.x, b0.y, b0.z, b0.w, b1.x, b1.y, b1.z, b1.w};
#pragma unroll
            for (int i = 0; i < 8; ++i)
#pragma unroll
                for (int j = 0; j < 8; ++j)
                    acc[i][j] += av[i] * bv[j];
        }
        __syncthreads();
    }
#pragma unroll
    for (int i = 0; i < 8; ++i) {
        int m = bm + ty * 8 + i;
        float* orow = outp + (size_t)m * G4 + j0 + tx * 8;
#pragma unroll
        for (int j = 0; j < 8; ++j)
            orow[j] = acc[i][j] + bias[j0 + tx * 8 + j];
    }
}

// ============================================================================
// Kernel 2: persistent bidirectional LSTM recurrence.
// 128 blocks: 0..63 forward, 64..127 backward. Block owns 4 hidden units
// (16 gate columns), w_hh tile resident in smem for all 256 steps.
// Per step: load h_prev[64x256] -> smem, GEMV-tile, gate nonlinearities,
// write h to global history, ticket spin-barrier across the 64 blocks.
// ============================================================================
__global__ void __launch_bounds__(256) lstm_kernel(
    const float* __restrict__ whhf, const float* __restrict__ whhb)
{
    extern __shared__ float sm[];
    float* ws   = sm;                       // [16][260] w tile (padded)
    float* hs   = sm + 16 * 260;            // [64][260] h_prev (padded)
    float* gbuf = sm + 16 * 260 + 64 * 260; // [16][65] gate exchange

    int tid = threadIdx.x;
    int dir = blockIdx.x >> 6;
    int blk = blockIdx.x & 63;
    int u0  = blk << 2;                     // 4 hidden units u0..u0+3
    const float* Whh = dir ? whhb : whhf;
    const float* xg  = dir ? g_xg_b : g_xg_f;
    float*       hh  = dir ? g_h_b  : g_h_f;

    // load weight tile: c = g*4+uu -> w_hh row g*256+u0+uu
    for (int idx = tid; idx < 16 * 256; idx += 256) {
        int c = idx >> 8, k = idx & 255;
        int g = c >> 2, uu = c & 3;
        ws[c * 260 + k] = Whh[(g * 256 + u0 + uu) * 256 + k];
    }

    int c  = tid & 15;              // column within 16
    int b0 = (tid >> 4) << 2;       // 4 batches b0..b0+3
    int gg = c >> 2, uu = c & 3;
    int colg = (gg << 8) + u0 + uu; // global gate column
    int ub = tid & 63, uq = tid >> 6; // update phase: (batch, unit)
    float creg = 0.f;               // cell state, thread-private
    unsigned long long* ctr = &g_bar[dir];

    const float4* wp  = (const float4*)(ws + c * 260);
    const float4* hq0 = (const float4*)(hs + (b0 + 0) * 260);
    const float4* hq1 = (const float4*)(hs + (b0 + 1) * 260);
    const float4* hq2 = (const float4*)(hs + (b0 + 2) * 260);
    const float4* hq3 = (const float4*)(hs + (b0 + 3) * 260);

    for (int it = 0; it < 256; ++it) {
        int s = dir ? (255 - it) : it;
        if (it == 0) {
            for (int idx = tid; idx < 64 * 256; idx += 256)
                hs[(idx >> 8) * 260 + (idx & 255)] = 0.f;
        } else {
            int sp = dir ? (s + 1) : (s - 1);
            const float4* src = (const float4*)hh + sp * 4096;
#pragma unroll
            for (int ch = 0; ch < 16; ++ch) {
                int f4 = (ch << 8) + tid;
                float4 v = src[f4];
                *(float4*)(hs + (f4 >> 6) * 260 + ((f4 & 63) << 2)) = v;
            }
        }
        __syncthreads();

        float a0 = 0.f, a1 = 0.f, a2 = 0.f, a3 = 0.f;
#pragma unroll 8
        for (int k4 = 0; k4 < 64; ++k4) {
            float4 w  = wp[k4];
            float4 h0 = hq0[k4];
            a0 += h0.x * w.x; a0 += h0.y * w.y; a0 += h0.z * w.z; a0 += h0.w * w.w;
            float4 h1 = hq1[k4];
            a1 += h1.x * w.x; a1 += h1.y * w.y; a1 += h1.z * w.z; a1 += h1.w * w.w;
            float4 h2 = hq2[k4];
            a2 += h2.x * w.x; a2 += h2.y * w.y; a2 += h2.z * w.z; a2 += h2.w * w.w;
            float4 h3 = hq3[k4];
            a3 += h3.x * w.x; a3 += h3.y * w.y; a3 += h3.z * w.z; a3 += h3.w * w.w;
        }
        int sb = s << 6;
        gbuf[c * 65 + b0 + 0] = a0 + xg[(size_t)(sb + b0 + 0) * G4 + colg];
        gbuf[c * 65 + b0 + 1] = a1 + xg[(size_t)(sb + b0 + 1) * G4 + colg];
        gbuf[c * 65 + b0 + 2] = a2 + xg[(size_t)(sb + b0 + 2) * G4 + colg];
        gbuf[c * 65 + b0 + 3] = a3 + xg[(size_t)(sb + b0 + 3) * G4 + colg];
        __syncthreads();

        // gate combine for (batch ub, unit uq); torch gate order i,f,g,o
        {
            float iv = gbuf[(uq     ) * 65 + ub];
            float fv = gbuf[(4  + uq) * 65 + ub];
            float gv = gbuf[(8  + uq) * 65 + ub];
            float ov = gbuf[(12 + uq) * 65 + ub];
            float si = 1.f / (1.f + __expf(-iv));
            float sf = 1.f / (1.f + __expf(-fv));
            float so = 1.f / (1.f + __expf(-ov));
            creg = sf * creg + si * tanhf(gv);
            float hv = so * tanhf(creg);
            hh[s * 16384 + ub * 256 + u0 + uq] = hv;
        }

        if (it != 255) {
            __threadfence();
            __syncthreads();
            if (tid == 0) {
                unsigned long long ticket = atomicAdd(ctr, 1ULL) + 1ULL;
                unsigned long long target = ((ticket + 63ULL) >> 6) << 6;
                while (*((volatile unsigned long long*)ctr) < target) { }
            }
            __syncthreads();
        }
    }
}

// ============================================================================
// Kernel 3: emissions. emit[b][s][t] = [hf|hb](s,b,:) . w_out[t,:] + b_out[t]
// Block = (s, half of batch). hidden tile in smem, float4 dots.
// ============================================================================
__global__ void __launch_bounds__(256) emis_kernel(
    const float* __restrict__ w_out, const float* __restrict__ b_out)
{
    extern __shared__ float4 hid4[];   // [32][130]  (128 f4 data + 2 pad)
    int s    = blockIdx.x >> 1;
    int half = blockIdx.x & 1;
    int tid  = threadIdx.x;

    const float4* hf4 = (const float4*)g_h_f + s * 4096 + half * 2048;
    const float4* hb4 = (const float4*)g_h_b + s * 4096 + half * 2048;
#pragma unroll
    for (int ch = 0; ch < 8; ++ch) {
        int f4 = ch * 256 + tid;
        int bl = f4 >> 6, k4 = f4 & 63;
        hid4[bl * 130 + k4]      = hf4[f4];
        hid4[bl * 130 + 64 + k4] = hb4[f4];
    }
    __syncthreads();

    for (int o = tid; o < 32 * TT; o += 256) {
        int bl = o / TT, t = o - bl * TT;
        const float4* wr = (const float4*)(w_out + t * 512);
        const float4* hr = hid4 + bl * 130;
        float acc = 0.f;
#pragma unroll 8
        for (int k4 = 0; k4 < 128; ++k4) {
            float4 h = hr[k4];
            float4 w = __ldg(wr + k4);
            acc += h.x * w.x + h.y * w.y + h.z * w.z + h.w * w.w;
        }
        int b = half * 32 + bl;
        g_emit[(b * SQ + s) * TT + t] = acc + __ldg(b_out + t);
    }
}

// ============================================================================
// Kernel 4: CRF NLL per batch (fully block-local forward algorithm).
// ============================================================================
__global__ void __launch_bounds__(64) crf_kernel(
    const int* __restrict__ tags,
    const float* __restrict__ start_t, const float* __restrict__ end_t,
    const float* __restrict__ trans)
{
    __shared__ float tr[TT * TT];
    __shared__ float buf0[TT], buf1[TT];
    __shared__ float red[64];
    int b = blockIdx.x, tid = threadIdx.x;

    for (int i = tid; i < TT * TT; i += 64) tr[i] = trans[i];
    const float* em = g_emit + (size_t)b * SQ * TT;
    if (tid < TT) buf0[tid] = start_t[tid] + em[tid];
    __syncthreads();

    float* cur = buf0;
    float* nxt = buf1;
    for (int s = 1; s < SQ; ++s) {
        if (tid < TT) {
            float m = -1e30f;
#pragma unroll
            for (int t = 0; t < TT; ++t) m = fmaxf(m, cur[t] + tr[t * TT + tid]);
            float sum = 0.f;
#pragma unroll
            for (int t = 0; t < TT; ++t) sum += __expf(cur[t] + tr[t * TT + tid] - m);
            nxt[tid] = m + __logf(sum) + em[s * TT + tid];
        }
        __syncthreads();
        float* tmp = cur; cur = nxt; nxt = tmp;
    }

    // numerator (gold path score), parallel over positions
    const int* tb = tags + b * SQ;
    float np = 0.f;
    for (int s = tid; s < SQ; s += 64)     np += em[s * TT + tb[s]];
    for (int s = tid; s < SQ - 1; s += 64) np += tr[tb[s] * TT + tb[s + 1]];
    red[tid] = np;
    __syncthreads();
    for (int o = 32; o > 0; o >>= 1) {
        if (tid < o) red[tid] += red[tid + o];
        __syncthreads();
    }
    if (tid == 0) {
        float m = -1e30f;
        for (int t = 0; t < TT; ++t) m = fmaxf(m, cur[t] + end_t[t]);
        float sum = 0.f;
        for (int t = 0; t < TT; ++t) sum += __expf(cur[t] + end_t[t] - m);
        float den = m + __logf(sum);
        float num = red[0] + start_t[tb[0]] + end_t[tb[SQ - 1]];
        g_llh[b] = num - den;
    }
}

// ============================================================================
// Kernel 5: final mean / negate.
// ============================================================================
__global__ void __launch_bounds__(64) finalize_kernel(float* out)
{
    __shared__ float r[64];
    int t = threadIdx.x;
    r[t] = g_llh[t];
    __syncthreads();
    for (int o = 32; o > 0; o >>= 1) {
        if (t < o) r[t] += r[t + o];
        __syncthreads();
    }
    if (t == 0) out[0] = -r[0] / 64.f;
}

// ============================================================================
extern "C" void kernel_launch(void* const* d_in, const int* in_sizes, int n_in,
                              void* d_out, int out_size)
{
    const int*   batch   = (const int*)  d_in[0];
    const int*   tags    = (const int*)  d_in[1];
    // d_in[2] seq_lengths: all == S, unused (mask is all-ones)
    const float* emb     = (const float*)d_in[3];
    const float* w_ih_f  = (const float*)d_in[4];
    const float* w_hh_f  = (const float*)d_in[5];
    const float* b_f     = (const float*)d_in[6];
    const float* w_ih_b  = (const float*)d_in[7];
    const float* w_hh_b  = (const float*)d_in[8];
    const float* b_b     = (const float*)d_in[9];
    const float* w_out   = (const float*)d_in[10];
    const float* b_out   = (const float*)d_in[11];
    const float* start_t = (const float*)d_in[12];
    const float* end_t   = (const float*)d_in[13];
    const float* trans   = (const float*)d_in[14];
    float* out = (float*)d_out;

    const int LSTM_SMEM = (16 * 260 + 64 * 260 + 16 * 65) * 4; // 87360 B
    const int EMIS_SMEM = 32 * 130 * 16;                       // 66560 B
    cudaFuncSetAttribute(lstm_kernel, cudaFuncAttributeMaxDynamicSharedMemorySize, LSTM_SMEM);
    cudaFuncSetAttribute(emis_kernel, cudaFuncAttributeMaxDynamicSharedMemorySize, EMIS_SMEM);

    input_gemm<<<dim3(16, 128), 256>>>(emb, batch, w_ih_f, b_f, w_ih_b, b_b);
    lstm_kernel<<<128, 256, LSTM_SMEM>>>(w_hh_f, w_hh_b);
    emis_kernel<<<512, 256, EMIS_SMEM>>>(w_out, b_out);
    crf_kernel<<<64, 64>>>(tags, start_t, end_t, trans);
    finalize_kernel<<<1, 64>>>(out);
}